// round 6
// baseline (speedup 1.0000x reference)
#include <cuda_runtime.h>

// Spline1DInterpolant: out[q] = sum_i c[i] * u(|s_q + 2 - (i+1)|),
// s = (x - a)/h, h = (b - a)/n. Cubic B-spline, support t < 2 => exactly 4
// consecutive taps per query: i = floor(s) .. floor(s)+3.
//
// Latency-bound (one wave, everything <2% of peak). Chain: LDG x (DRAM) ->
// div/floor -> gather c -> STG. c is only 16KB = 128 lines: ALL 128 threads of
// each block prefetch one line into this SM's L1, non-blocking and independent
// of x, fully overlapped with the x load. Dependent gathers then hit L1
// (~39cyc) instead of L2 (~250cyc) / DRAM (~600cyc).

__device__ __forceinline__ float bspline_basis(float t) {
    // t in [0,2]; inner (t<=1): 4 - 6t^2 + 3t^3 ; outer: (2-t)^3
    float t2 = t * t;
    float inner = 4.0f - 6.0f * t2 + 3.0f * t2 * t;
    float om = 2.0f - t;
    float outer = om * om * om;
    return (t <= 1.0f) ? inner : outer;
}

__global__ void __launch_bounds__(128)
spline1d_kernel(const float* __restrict__ x,
                const float* __restrict__ a,
                const float* __restrict__ b,
                const float* __restrict__ n,
                const float* __restrict__ c,
                float* __restrict__ out,
                int nb, int nc) {
    // Per-SM L1 prefetch of the whole coefficient table (16KB = 128 lines),
    // one 128B line per thread. Non-blocking; independent of x.
    {
        int line = threadIdx.x * 32;              // float index of a 128B line
        if (line < nc) {
            asm volatile("prefetch.global.L1 [%0];" :: "l"(c + line));
        }
        // nc > 4096 fallback coverage: stride over remaining lines.
        for (int l = (128 + threadIdx.x) * 32; l < nc; l += 128 * 32) {
            asm volatile("prefetch.global.L1 [%0];" :: "l"(c + l));
        }
    }

    int tid = blockIdx.x * 128 + threadIdx.x;
    if (tid >= nb) return;

    // Reference-exact arithmetic (fp32, true division).
    float xq = __ldg(x + tid);
    float a0 = __ldg(a);
    float h  = (__ldg(b) - a0) / __ldg(n);
    float s  = (xq - a0) / h;

    int i0 = (int)floorf(s);

    float sum = 0.0f;
#pragma unroll
    for (int k = 0; k < 4; k++) {
        int i = i0 + k;
        float t = fabsf(s + 2.0f - (float)(i + 1));   // same cancellation as ref
        float u = bspline_basis(t);
        if ((unsigned)i < (unsigned)nc) {
            sum = fmaf(__ldg(c + i), u, sum);
        }
    }
    out[tid] = sum;
}

extern "C" void kernel_launch(void* const* d_in, const int* in_sizes, int n_in,
                              void* d_out, int out_size) {
    const float* x = (const float*)d_in[0];   // [B,1] fp32
    const float* a = (const float*)d_in[1];   // [1]
    const float* b = (const float*)d_in[2];   // [1]
    const float* n = (const float*)d_in[3];   // [1]
    const float* c = (const float*)d_in[4];   // [C]
    float* out = (float*)d_out;

    int nb = in_sizes[0];      // 16384
    int nc = in_sizes[4];      // 4096

    int blocks = (nb + 127) / 128;            // 128 blocks, one wave
    spline1d_kernel<<<blocks, 128>>>(x, a, b, n, c, out, nb, nc);
}